// round 16
// baseline (speedup 1.0000x reference)
#include <cuda_runtime.h>
#include <cuda_bf16.h>
#include <cuda_fp16.h>
#include <cstdint>

#define HIDDEN   1024
#define BATCH    2
#define SEQ      2048
#define NHEADS   16
#define HDIM     64
#define MROWS    (BATCH * SEQ)   // 4096
#define KDIM     1024
#define K3       (3 * KDIM)      // 3072 (split-bf16 concatenated K)

// ---------------------------------------------------------------------------
// Scratch (static device globals — no runtime allocation allowed)
// ---------------------------------------------------------------------------
__device__ __align__(256) __nv_bfloat16 g_a3x[MROWS * K3];        // x split
__device__ __align__(256) __nv_bfloat16 g_a3o[MROWS * K3];        // attn-out split
__device__ __align__(256) __nv_bfloat16 g_b3q[3 * HIDDEN * K3];   // W_qkv split
__device__ __align__(256) __nv_bfloat16 g_b3o[HIDDEN * K3];       // W_o split

// Attention operands (written by QKV GEMM epilogue):
//   g_q2/g_k2: [B*H][N][ hi(64) | lo(64) ] bf16   (Q pre-scaled by 0.125*log2e)
//   g_vth/g_vtl: [B*H][d=64][N] fp16 (transposed V, hi/lo)
__device__ __align__(256) __nv_bfloat16 g_q2 [BATCH * NHEADS * SEQ * 128];
__device__ __align__(256) __nv_bfloat16 g_k2 [BATCH * NHEADS * SEQ * 128];
__device__ __align__(256) __half        g_vth[BATCH * NHEADS * 64 * SEQ];
__device__ __align__(256) __half        g_vtl[BATCH * NHEADS * 64 * SEQ];

// ---------------------------------------------------------------------------
// PTX helpers (baseline sm_100 safe)
// ---------------------------------------------------------------------------
__device__ __forceinline__ uint32_t smem_u32(const void* p) {
    uint32_t a;
    asm("{ .reg .u64 t; cvta.to.shared.u64 t, %1; cvt.u32.u64 %0, t; }" : "=r"(a) : "l"(p));
    return a;
}
__device__ __forceinline__ float ex2f(float x) {
    float y; asm("ex2.approx.ftz.f32 %0, %1;" : "=f"(y) : "f"(x)); return y;
}

#define CP_ASYNC16(dst, src) \
    asm volatile("cp.async.cg.shared.global [%0], [%1], 16;" :: "r"(dst), "l"(src) : "memory")
#define CP_COMMIT() asm volatile("cp.async.commit_group;" ::: "memory")
#define CP_WAIT(n)  asm volatile("cp.async.wait_group %0;" :: "n"(n) : "memory")

#define LDSM_X4(r0, r1, r2, r3, addr) \
    asm volatile("ldmatrix.sync.aligned.m8n8.x4.shared.b16 {%0,%1,%2,%3}, [%4];" \
        : "=r"(r0), "=r"(r1), "=r"(r2), "=r"(r3) : "r"(addr))

#define MMA_BF16(d, a, b0, b1) \
    asm volatile("mma.sync.aligned.m16n8k16.row.col.f32.bf16.bf16.f32 " \
        "{%0,%1,%2,%3}, {%4,%5,%6,%7}, {%8,%9}, {%0,%1,%2,%3};" \
        : "+f"((d)[0]), "+f"((d)[1]), "+f"((d)[2]), "+f"((d)[3]) \
        : "r"((a)[0]), "r"((a)[1]), "r"((a)[2]), "r"((a)[3]), "r"(b0), "r"(b1))

#define MMA_F16(d, a, b0, b1) \
    asm volatile("mma.sync.aligned.m16n8k16.row.col.f32.f16.f16.f32 " \
        "{%0,%1,%2,%3}, {%4,%5,%6,%7}, {%8,%9}, {%0,%1,%2,%3};" \
        : "+f"((d)[0]), "+f"((d)[1]), "+f"((d)[2]), "+f"((d)[3]) \
        : "r"((a)[0]), "r"((a)[1]), "r"((a)[2]), "r"((a)[3]), "r"(b0), "r"(b1))

// ---------------------------------------------------------------------------
// fp32 -> split-bf16 concatenated layout.
// dst_sel: 0 = g_a3x (src=x), 1 = g_b3q, 2 = g_b3o
// A layout: hi @ c, c+2048 ; lo @ c+1024.   B layout: hi @ c, c+1024 ; lo @ c+2048
// ---------------------------------------------------------------------------
__global__ void split3_kernel(const float4* __restrict__ src, int dst_sel, int n4)
{
    int i = blockIdx.x * blockDim.x + threadIdx.x;
    if (i >= n4) return;
    __nv_bfloat16* dst = (dst_sel == 0) ? g_a3x :
                         (dst_sel == 1) ? g_b3q : g_b3o;
    const int off_hi1 = (dst_sel == 0) ? 2048 : 1024;
    const int off_lo  = (dst_sel == 0) ? 1024 : 2048;

    const int r = i >> 8;
    const int c = (i & 255) << 2;

    float4 v = src[i];
    __nv_bfloat162 hA = __floats2bfloat162_rn(v.x, v.y);
    __nv_bfloat162 hB = __floats2bfloat162_rn(v.z, v.w);
    __nv_bfloat162 lA = __floats2bfloat162_rn(v.x - __low2float(hA), v.y - __high2float(hA));
    __nv_bfloat162 lB = __floats2bfloat162_rn(v.z - __low2float(hB), v.w - __high2float(hB));
    uint2 H, L;
    H.x = *reinterpret_cast<const uint32_t*>(&hA);
    H.y = *reinterpret_cast<const uint32_t*>(&hB);
    L.x = *reinterpret_cast<const uint32_t*>(&lA);
    L.y = *reinterpret_cast<const uint32_t*>(&lB);

    uint2* base = (uint2*)(dst + (size_t)r * K3);
    base[(c) >> 2]           = H;
    base[(off_hi1 + c) >> 2] = H;
    base[(off_lo  + c) >> 2] = L;
}

// ---------------------------------------------------------------------------
// bf16 mma.sync GEMM: 128x128 tile, BK=64, 3-stage cp.async pipeline,
// __launch_bounds__(256,2): 2 CTAs/SM. Next-stage loads issued BEFORE compute.
// qkv=1: epilogue -> split Q (pre-scaled by 0.125*log2e) / K (bf16) +
//        transposed split V (fp16)
// qkv=0: plain C write + bias
// ---------------------------------------------------------------------------
#define BK      64
#define NSTG    3
#define KC      (K3 / BK)          // 48
#define TILEB   (128 * BK * 2)     // 16384
#define STAGEB  (2 * TILEB)        // 32768
#define GEMM_SMEM (NSTG * STAGEB)  // 98304

#define CSF     0.18033688011112042f   // 0.125 * log2(e), folded into Q

__global__ __launch_bounds__(256, 2)
void gemm_mma(const float* __restrict__ bias, float* __restrict__ C, int qkv)
{
    extern __shared__ __align__(1024) char smem[];
    const uint32_t sb = smem_u32(smem);

    const int tid  = threadIdx.x;
    const int lane = tid & 31;
    const int wid  = tid >> 5;
    const int wm   = wid & 1;
    const int wn   = wid >> 1;
    const int bm   = blockIdx.y * 128;
    const int bn   = blockIdx.x * 128;

    const __nv_bfloat16* Aop = qkv ? g_a3x : g_a3o;
    const __nv_bfloat16* Bop = qkv ? g_b3q : g_b3o;

    const int a_row_l = (lane & 7) | (((lane >> 3) & 1) << 3);
    const int a_kb    = (lane >> 4) << 4;
    const int b_row_l = (lane & 7) | (((lane >> 4) & 1) << 3);
    const int b_kb    = ((lane >> 3) & 1) << 4;
    const uint32_t axor = (uint32_t)(a_row_l & 7) << 4;
    const uint32_t bxor = (uint32_t)(b_row_l & 7) << 4;

    float acc[4][4][4];
#pragma unroll
    for (int m = 0; m < 4; m++)
#pragma unroll
        for (int n = 0; n < 4; n++)
#pragma unroll
            for (int r = 0; r < 4; r++) acc[m][n][r] = 0.f;

    auto load_stage = [&](int s, int kc) {
        const uint32_t stg = sb + (uint32_t)s * STAGEB;
#pragma unroll
        for (int i = 0; i < 4; i++) {
            const int idx = tid + i * 256;
            const int row = idx >> 3;
            const int c16 = idx & 7;
            const uint32_t sw = (uint32_t)row * 128 + (((uint32_t)c16 << 4) ^ ((uint32_t)(row & 7) << 4));
            CP_ASYNC16(stg + sw,
                       (const char*)(Aop + (size_t)(bm + row) * K3 + kc) + c16 * 16);
            CP_ASYNC16(stg + TILEB + sw,
                       (const char*)(Bop + (size_t)(bn + row) * K3 + kc) + c16 * 16);
        }
    };

    load_stage(0, 0);      CP_COMMIT();
    load_stage(1, BK);     CP_COMMIT();

    for (int c = 0; c < KC; c++) {
        CP_WAIT(NSTG - 2);
        __syncthreads();

        // issue next-stage loads first so they overlap this chunk's MMAs
        const int nc = c + NSTG - 1;
        if (nc < KC) load_stage(nc % NSTG, nc * BK);
        CP_COMMIT();

        const int s = c % NSTG;
        const uint32_t sA = sb + (uint32_t)s * STAGEB;
        const uint32_t sB = sA + TILEB;

#pragma unroll
        for (int kk = 0; kk < 4; kk++) {
            uint32_t a[4][4], b[2][4];
#pragma unroll
            for (int mf = 0; mf < 4; mf++)
                LDSM_X4(a[mf][0], a[mf][1], a[mf][2], a[mf][3],
                        sA + (uint32_t)(wm * 64 + mf * 16 + a_row_l) * 128
                           + (((uint32_t)(kk * 32 + a_kb)) ^ axor));
#pragma unroll
            for (int nf2 = 0; nf2 < 2; nf2++)
                LDSM_X4(b[nf2][0], b[nf2][1], b[nf2][2], b[nf2][3],
                        sB + (uint32_t)(wn * 32 + nf2 * 16 + b_row_l) * 128
                           + (((uint32_t)(kk * 32 + b_kb)) ^ bxor));
#pragma unroll
            for (int mf = 0; mf < 4; mf++)
#pragma unroll
                for (int nf = 0; nf < 4; nf++)
                    MMA_BF16(acc[mf][nf], a[mf],
                             b[nf >> 1][(nf & 1) * 2], b[nf >> 1][(nf & 1) * 2 + 1]);
        }
    }

    // ------------------ epilogue ------------------
    const int g  = lane >> 2;
    const int cp = (lane & 3) * 2;

#pragma unroll
    for (int mf = 0; mf < 4; mf++) {
#pragma unroll
        for (int half = 0; half < 2; half++) {
            const int row = bm + wm * 64 + mf * 16 + g + half * 8;
#pragma unroll
            for (int nf = 0; nf < 4; nf++) {
                const int col = bn + wn * 32 + nf * 8 + cp;
                float2 o;
                o.x = acc[mf][nf][half * 2 + 0] + bias[col];
                o.y = acc[mf][nf][half * 2 + 1] + bias[col + 1];
                if (qkv) {
                    const int bb = row >> 11;
                    const int n  = row & 2047;
                    const int pt = col >> 10;
                    const int c1 = col & 1023;
                    const int hh = c1 >> 6;
                    const int hd = c1 & 63;          // even
                    const int bh = bb * NHEADS + hh;
                    if (pt < 2) {
                        if (pt == 0) { o.x *= CSF; o.y *= CSF; }   // fold softmax scale into Q
                        __nv_bfloat162 hv = __floats2bfloat162_rn(o.x, o.y);
                        __nv_bfloat162 lv = __floats2bfloat162_rn(
                            o.x - __bfloat162float(hv.x), o.y - __bfloat162float(hv.y));
                        __nv_bfloat16* dst = pt ? g_k2 : g_q2;
                        const size_t base = ((size_t)bh * SEQ + n) * 128;
                        *(__nv_bfloat162*)&dst[base + hd]      = hv;
                        *(__nv_bfloat162*)&dst[base + 64 + hd] = lv;
                    } else {
                        __half2 hv = __floats2half2_rn(o.x, o.y);
                        __half2 lv = __floats2half2_rn(
                            o.x - __half2float(__low2half(hv)),
                            o.y - __half2float(__high2half(hv)));
                        const size_t vb = ((size_t)bh * 64 + hd) * SEQ + n;
                        g_vth[vb]       = __low2half(hv);
                        g_vth[vb + SEQ] = __high2half(hv);
                        g_vtl[vb]       = __low2half(lv);
                        g_vtl[vb + SEQ] = __high2half(lv);
                    }
                } else {
                    *(float2*)&C[(size_t)row * HIDDEN + col] = o;
                }
            }
        }
    }
}

// ---------------------------------------------------------------------------
// Flash attention: QK^T bf16 3-term (merged single pass), PV fp16 2-term.
// Round 16: Q fragments cached in registers for the WHOLE kernel (one smem
// read in the prologue) — per-tile LDSM 76 -> 64; softmax scale pre-folded
// into Q. 2-stage K/V pipeline, 2 CTAs/SM.
// ---------------------------------------------------------------------------
#define NT        (SEQ / 64)       // 32 key tiles
#define ASTG_OFF  32768
#define ASTG_SZ   32768
#define ATTN2_SMEM (32768 + 2 * ASTG_SZ)   // 98304

__global__ __launch_bounds__(256, 2)
void attn_mma()
{
    extern __shared__ __align__(1024) char smem[];
    const uint32_t sb = smem_u32(smem);
    const int tid = threadIdx.x, lane = tid & 31, wid = tid >> 5;
    const int qt = blockIdx.x, h = blockIdx.y, b = blockIdx.z;
    const int bh = b * NHEADS + h;

    const __nv_bfloat16* q2p = g_q2 + ((size_t)bh * SEQ + qt * 128) * 128;
    const __nv_bfloat16* k2p = g_k2 + (size_t)bh * SEQ * 128;
    const __half* vhp = g_vth + (size_t)bh * 64 * SEQ;
    const __half* vlp = g_vtl + (size_t)bh * 64 * SEQ;

    auto load_stage = [&](int kt) {
        const uint32_t stg = sb + ASTG_OFF + (uint32_t)(kt & 1) * ASTG_SZ;
#pragma unroll
        for (int i = 0; i < 8; i++) {
            const int idx = tid + i * 256;                 // 0..2047
            if (idx < 1024) {                              // k2: 64 rows x 16 chunks
                const int row = idx >> 4, c16 = idx & 15;
                CP_ASYNC16(stg + row * 256 + (((uint32_t)c16 << 4) ^ ((uint32_t)(row & 7) << 4)),
                           (const char*)(k2p + (size_t)(kt * 64 + row) * 128) + c16 * 16);
            } else {                                       // vt: 64 d-rows x [Vh 8 | Vl 8] (fp16)
                const int j = idx - 1024;
                const int row = j >> 4, c16 = j & 15;
                const __half* src = (c16 < 8) ? vhp : vlp;
                CP_ASYNC16(stg + 16384 + row * 256 + (((uint32_t)c16 << 4) ^ ((uint32_t)(row & 7) << 4)),
                           (const char*)(src + (size_t)row * SEQ + kt * 64) + (c16 & 7) * 16);
            }
        }
    };

    // Q tile (128 rows x 16 chunks) + first K/V stage in one commit group
#pragma unroll
    for (int i = 0; i < 8; i++) {
        const int idx = tid + i * 256;
        const int row = idx >> 4, c16 = idx & 15;
        CP_ASYNC16(sb + row * 256 + (((uint32_t)c16 << 4) ^ ((uint32_t)(row & 7) << 4)),
                   (const char*)(q2p + (size_t)row * 128) + c16 * 16);
    }
    load_stage(0); CP_COMMIT();

    const int a_row = wid * 16 + ((lane & 7) | (((lane >> 3) & 1) << 3));
    const int a_kb  = lane >> 4;
    const int b_rl  = (lane & 7) | (((lane >> 4) & 1) << 3);
    const int b_kb  = (lane >> 3) & 1;
    const uint32_t a_sw = (uint32_t)(a_row & 7) << 4;
    const uint32_t qbase = sb + (uint32_t)a_row * 256;

    // ---- prologue: wait for Q + stage 0, cache Q fragments in registers ----
    CP_WAIT(0);
    __syncthreads();
    uint32_t qh[4][4], ql[4][4];
#pragma unroll
    for (int kk = 0; kk < 4; kk++) {
        LDSM_X4(qh[kk][0], qh[kk][1], qh[kk][2], qh[kk][3],
                qbase + (((uint32_t)(kk * 2 + a_kb) << 4) ^ a_sw));
        LDSM_X4(ql[kk][0], ql[kk][1], ql[kk][2], ql[kk][3],
                qbase + (((uint32_t)(8 + kk * 2 + a_kb) << 4) ^ a_sw));
    }

    float oacc[8][4];
#pragma unroll
    for (int nf = 0; nf < 8; nf++)
#pragma unroll
        for (int e = 0; e < 4; e++) oacc[nf][e] = 0.f;
    float m0 = -1e30f, m1 = -1e30f, l0 = 0.f, l1 = 0.f;

    for (int kt = 0; kt < NT; kt++) {
        if (kt > 0) {
            CP_WAIT(0);        // stage kt resident
            __syncthreads();   // all warps done with stage kt-1
        }
        if (kt + 1 < NT) { load_stage(kt + 1); CP_COMMIT(); }

        const uint32_t sk = sb + ASTG_OFF + (uint32_t)(kt & 1) * ASTG_SZ;
        const uint32_t sv = sk + 16384;

        // ---- S = Qh·Kh + Ql·Kh + Qh·Kl (bf16, merged single pass) ----
        float s[8][4];
#pragma unroll
        for (int nf = 0; nf < 8; nf++)
#pragma unroll
            for (int e = 0; e < 4; e++) s[nf][e] = 0.f;

#pragma unroll
        for (int kk = 0; kk < 4; kk++) {
#pragma unroll
            for (int nb = 0; nb < 4; nb++) {
                const int br = nb * 16 + b_rl;
                const uint32_t brow = sk + (uint32_t)br * 256;
                const uint32_t bsw  = (uint32_t)(br & 7) << 4;
                uint32_t bk[4];
                LDSM_X4(bk[0], bk[1], bk[2], bk[3],
                        brow + (((uint32_t)(kk * 2 + b_kb) << 4) ^ bsw));
                MMA_BF16(s[2 * nb],     qh[kk], bk[0], bk[1]);
                MMA_BF16(s[2 * nb + 1], qh[kk], bk[2], bk[3]);
                MMA_BF16(s[2 * nb],     ql[kk], bk[0], bk[1]);
                MMA_BF16(s[2 * nb + 1], ql[kk], bk[2], bk[3]);
                LDSM_X4(bk[0], bk[1], bk[2], bk[3],
                        brow + (((uint32_t)(8 + kk * 2 + b_kb) << 4) ^ bsw));
                MMA_BF16(s[2 * nb],     qh[kk], bk[0], bk[1]);
                MMA_BF16(s[2 * nb + 1], qh[kk], bk[2], bk[3]);
            }
        }

        // ---- online softmax (fp32; scale already folded into Q) ----
        float rm0 = s[0][0], rm1 = s[0][2];
#pragma unroll
        for (int nf = 0; nf < 8; nf++) {
            rm0 = fmaxf(rm0, fmaxf(s[nf][0], s[nf][1]));
            rm1 = fmaxf(rm1, fmaxf(s[nf][2], s[nf][3]));
        }
        rm0 = fmaxf(rm0, __shfl_xor_sync(0xffffffffu, rm0, 1));
        rm0 = fmaxf(rm0, __shfl_xor_sync(0xffffffffu, rm0, 2));
        rm1 = fmaxf(rm1, __shfl_xor_sync(0xffffffffu, rm1, 1));
        rm1 = fmaxf(rm1, __shfl_xor_sync(0xffffffffu, rm1, 2));
        const float mn0 = fmaxf(m0, rm0);
        const float mn1 = fmaxf(m1, rm1);
        const float cr0 = ex2f(m0 - mn0);
        const float cr1 = ex2f(m1 - mn1);
        float sum0 = 0.f, sum1 = 0.f;
#pragma unroll
        for (int nf = 0; nf < 8; nf++) {
            s[nf][0] = ex2f(s[nf][0] - mn0);
            s[nf][1] = ex2f(s[nf][1] - mn0);
            s[nf][2] = ex2f(s[nf][2] - mn1);
            s[nf][3] = ex2f(s[nf][3] - mn1);
            sum0 += s[nf][0] + s[nf][1];
            sum1 += s[nf][2] + s[nf][3];
        }
        sum0 += __shfl_xor_sync(0xffffffffu, sum0, 1);
        sum0 += __shfl_xor_sync(0xffffffffu, sum0, 2);
        sum1 += __shfl_xor_sync(0xffffffffu, sum1, 1);
        sum1 += __shfl_xor_sync(0xffffffffu, sum1, 2);
        l0 = l0 * cr0 + sum0;  l1 = l1 * cr1 + sum1;
        m0 = mn0;  m1 = mn1;
#pragma unroll
        for (int nf = 0; nf < 8; nf++) {
            oacc[nf][0] *= cr0; oacc[nf][1] *= cr0;
            oacc[nf][2] *= cr1; oacc[nf][3] *= cr1;
        }

        // ---- P -> fp16 A-fragments (single precision, registers) ----
        uint32_t ph[4][4];
#pragma unroll
        for (int t = 0; t < 4; t++) {
#pragma unroll
            for (int hf = 0; hf < 2; hf++) {
                const int j = 2 * t + hf;
                __half2 p0 = __floats2half2_rn(s[j][0], s[j][1]);
                __half2 p1 = __floats2half2_rn(s[j][2], s[j][3]);
                ph[t][hf * 2 + 0] = *reinterpret_cast<uint32_t*>(&p0);
                ph[t][hf * 2 + 1] = *reinterpret_cast<uint32_t*>(&p1);
            }
        }

        // ---- O += P·Vh (fp16), then O += P·Vl — split passes to cap regs ----
#pragma unroll
        for (int t = 0; t < 4; t++) {
            uint32_t bv[4][4];
#pragma unroll
            for (int nb = 0; nb < 4; nb++) {
                const int br = nb * 16 + b_rl;
                LDSM_X4(bv[nb][0], bv[nb][1], bv[nb][2], bv[nb][3],
                        sv + (uint32_t)br * 256 + (((uint32_t)(t * 2 + b_kb) << 4) ^ ((uint32_t)(br & 7) << 4)));
            }
#pragma unroll
            for (int nf = 0; nf < 8; nf++)
                MMA_F16(oacc[nf], ph[t], bv[nf >> 1][(nf & 1) * 2], bv[nf >> 1][(nf & 1) * 2 + 1]);
        }
#pragma unroll
        for (int t = 0; t < 4; t++) {
            uint32_t bv[4][4];
#pragma unroll
            for (int nb = 0; nb < 4; nb++) {
                const int br = nb * 16 + b_rl;
                LDSM_X4(bv[nb][0], bv[nb][1], bv[nb][2], bv[nb][3],
                        sv + (uint32_t)br * 256 + (((uint32_t)(8 + t * 2 + b_kb) << 4) ^ ((uint32_t)(br & 7) << 4)));
            }
#pragma unroll
            for (int nf = 0; nf < 8; nf++)
                MMA_F16(oacc[nf], ph[t], bv[nf >> 1][(nf & 1) * 2], bv[nf >> 1][(nf & 1) * 2 + 1]);
        }
    }

    // ---- epilogue: normalize, write split-concat A3 layout for O-proj ----
    const int g = lane >> 2, cp2 = (lane & 3) * 2;
    const float i0 = 1.f / l0, i1 = 1.f / l1;
    const size_t r0 = (size_t)b * SEQ + qt * 128 + wid * 16 + g;
#pragma unroll
    for (int nf = 0; nf < 8; nf++) {
        const int col = h * 64 + nf * 8 + cp2;
        float2 u, v;
        u.x = oacc[nf][0] * i0;  u.y = oacc[nf][1] * i0;
        v.x = oacc[nf][2] * i1;  v.y = oacc[nf][3] * i1;

        __nv_bfloat162 uh = __floats2bfloat162_rn(u.x, u.y);
        __nv_bfloat162 ul = __floats2bfloat162_rn(u.x - __low2float(uh), u.y - __high2float(uh));
        __nv_bfloat162 vh = __floats2bfloat162_rn(v.x, v.y);
        __nv_bfloat162 vl = __floats2bfloat162_rn(v.x - __low2float(vh), v.y - __high2float(vh));

        __nv_bfloat16* d0 = g_a3o + r0 * K3;
        __nv_bfloat16* d1 = g_a3o + (r0 + 8) * K3;
        *(__nv_bfloat162*)&d0[col]        = uh;
        *(__nv_bfloat162*)&d0[col + 2048] = uh;
        *(__nv_bfloat162*)&d0[col + 1024] = ul;
        *(__nv_bfloat162*)&d1[col]        = vh;
        *(__nv_bfloat162*)&d1[col + 2048] = vh;
        *(__nv_bfloat162*)&d1[col + 1024] = vl;
    }
}

// ---------------------------------------------------------------------------
// Launch
// ---------------------------------------------------------------------------
extern "C" void kernel_launch(void* const* d_in, const int* in_sizes, int n_in,
                              void* d_out, int out_size)
{
    const float* x    = (const float*)d_in[0];
    const float* Wqkv = (const float*)d_in[1];
    const float* bqkv = (const float*)d_in[2];
    const float* Wo   = (const float*)d_in[3];
    const float* bo   = (const float*)d_in[4];
    float* out = (float*)d_out;

    cudaFuncSetAttribute(gemm_mma, cudaFuncAttributeMaxDynamicSharedMemorySize, GEMM_SMEM);
    cudaFuncSetAttribute(attn_mma, cudaFuncAttributeMaxDynamicSharedMemorySize, ATTN2_SMEM);

    // split inputs into concatenated hi/lo bf16 layout
    split3_kernel<<<MROWS, 256>>>((const float4*)x,    0, MROWS * 256);
    split3_kernel<<<3 * HIDDEN, 256>>>((const float4*)Wqkv, 1, 3 * HIDDEN * 256);
    split3_kernel<<<HIDDEN, 256>>>((const float4*)Wo,  2, HIDDEN * 256);

    // QKV projection -> split attention operands (q2 scaled, k2 bf16, vth/vtl fp16)
    gemm_mma<<<dim3(3 * HIDDEN / 128, MROWS / 128), 256, GEMM_SMEM>>>(bqkv, nullptr, 1);

    // attention on tensor cores -> split O-proj A operand (g_a3o)
    attn_mma<<<dim3(SEQ / 128, NHEADS, BATCH), 256, ATTN2_SMEM>>>();

    // O-projection
    gemm_mma<<<dim3(HIDDEN / 128, MROWS / 128), 256, GEMM_SMEM>>>(bo, out, 0);
}

// round 17
// speedup vs baseline: 1.2284x; 1.2284x over previous
#include <cuda_runtime.h>
#include <cuda_bf16.h>
#include <cuda_fp16.h>
#include <cstdint>

#define HIDDEN   1024
#define BATCH    2
#define SEQ      2048
#define NHEADS   16
#define HDIM     64
#define MROWS    (BATCH * SEQ)   // 4096
#define KDIM     1024
#define K2       (2 * KDIM)      // 2048 (fp16 2-term concatenated K)

// ---------------------------------------------------------------------------
// Scratch (static device globals — no runtime allocation allowed)
// ---------------------------------------------------------------------------
// fp16 2-term GEMM operands: A = [act_hi | act_lo], B = [W | W]
__device__ __align__(256) __half g_a2x[MROWS * K2];          // x split (fp16 hi/lo)
__device__ __align__(256) __half g_a2o[MROWS * K2];          // attn-out split (written by attn epilogue)
__device__ __align__(256) __half g_b2q[3 * HIDDEN * K2];     // W_qkv single fp16, duplicated
__device__ __align__(256) __half g_b2o[HIDDEN * K2];         // W_o   single fp16, duplicated

// Attention operands (written by QKV GEMM epilogue):
//   g_q2/g_k2: [B*H][N][ hi(64) | lo(64) ] bf16   (Q pre-scaled by 0.125*log2e)
//   g_vth/g_vtl: [B*H][d=64][N] fp16 (transposed V, hi/lo)
__device__ __align__(256) __nv_bfloat16 g_q2 [BATCH * NHEADS * SEQ * 128];
__device__ __align__(256) __nv_bfloat16 g_k2 [BATCH * NHEADS * SEQ * 128];
__device__ __align__(256) __half        g_vth[BATCH * NHEADS * 64 * SEQ];
__device__ __align__(256) __half        g_vtl[BATCH * NHEADS * 64 * SEQ];

// ---------------------------------------------------------------------------
// PTX helpers (baseline sm_100 safe)
// ---------------------------------------------------------------------------
__device__ __forceinline__ uint32_t smem_u32(const void* p) {
    uint32_t a;
    asm("{ .reg .u64 t; cvta.to.shared.u64 t, %1; cvt.u32.u64 %0, t; }" : "=r"(a) : "l"(p));
    return a;
}
__device__ __forceinline__ float ex2f(float x) {
    float y; asm("ex2.approx.ftz.f32 %0, %1;" : "=f"(y) : "f"(x)); return y;
}

#define CP_ASYNC16(dst, src) \
    asm volatile("cp.async.cg.shared.global [%0], [%1], 16;" :: "r"(dst), "l"(src) : "memory")
#define CP_COMMIT() asm volatile("cp.async.commit_group;" ::: "memory")
#define CP_WAIT(n)  asm volatile("cp.async.wait_group %0;" :: "n"(n) : "memory")

#define LDSM_X4(r0, r1, r2, r3, addr) \
    asm volatile("ldmatrix.sync.aligned.m8n8.x4.shared.b16 {%0,%1,%2,%3}, [%4];" \
        : "=r"(r0), "=r"(r1), "=r"(r2), "=r"(r3) : "r"(addr))

#define MMA_BF16(d, a, b0, b1) \
    asm volatile("mma.sync.aligned.m16n8k16.row.col.f32.bf16.bf16.f32 " \
        "{%0,%1,%2,%3}, {%4,%5,%6,%7}, {%8,%9}, {%0,%1,%2,%3};" \
        : "+f"((d)[0]), "+f"((d)[1]), "+f"((d)[2]), "+f"((d)[3]) \
        : "r"((a)[0]), "r"((a)[1]), "r"((a)[2]), "r"((a)[3]), "r"(b0), "r"(b1))

#define MMA_F16(d, a, b0, b1) \
    asm volatile("mma.sync.aligned.m16n8k16.row.col.f32.f16.f16.f32 " \
        "{%0,%1,%2,%3}, {%4,%5,%6,%7}, {%8,%9}, {%0,%1,%2,%3};" \
        : "+f"((d)[0]), "+f"((d)[1]), "+f"((d)[2]), "+f"((d)[3]) \
        : "r"((a)[0]), "r"((a)[1]), "r"((a)[2]), "r"((a)[3]), "r"(b0), "r"(b1))

// ---------------------------------------------------------------------------
// fp32 -> fp16 2-term layout.
// dst_sel 0: x -> g_a2x as [hi @ c | lo @ c+1024]
// dst_sel 1: Wqkv -> g_b2q as [W @ c | W @ c+1024] (single fp16, duplicated)
// dst_sel 2: Wo   -> g_b2o likewise
// ---------------------------------------------------------------------------
__global__ void split2_kernel(const float4* __restrict__ src, int dst_sel, int n4)
{
    int i = blockIdx.x * blockDim.x + threadIdx.x;
    if (i >= n4) return;
    __half* dst = (dst_sel == 0) ? g_a2x :
                  (dst_sel == 1) ? g_b2q : g_b2o;

    const int r = i >> 8;            // 256 float4 per 1024-col source row
    const int c = (i & 255) << 2;

    float4 v = src[i];
    __half2 hA = __floats2half2_rn(v.x, v.y);
    __half2 hB = __floats2half2_rn(v.z, v.w);
    uint2 H;
    H.x = *reinterpret_cast<const uint32_t*>(&hA);
    H.y = *reinterpret_cast<const uint32_t*>(&hB);

    uint2* base = (uint2*)(dst + (size_t)r * K2);
    base[c >> 2] = H;
    if (dst_sel == 0) {
        __half2 lA = __floats2half2_rn(v.x - __half2float(__low2half(hA)),
                                       v.y - __half2float(__high2half(hA)));
        __half2 lB = __floats2half2_rn(v.z - __half2float(__low2half(hB)),
                                       v.w - __half2float(__high2half(hB)));
        uint2 L;
        L.x = *reinterpret_cast<const uint32_t*>(&lA);
        L.y = *reinterpret_cast<const uint32_t*>(&lB);
        base[(1024 + c) >> 2] = L;
    } else {
        base[(1024 + c) >> 2] = H;
    }
}

// ---------------------------------------------------------------------------
// fp16 mma.sync GEMM: C[M,N] = A2[M,K2] @ B2[N,K2]^T + bias
// 128x128 tile, BK=64, 3-stage cp.async pipeline (R15-proven order:
// loads issued AFTER compute). __launch_bounds__(256,2): 2 CTAs/SM.
// qkv=1: epilogue -> split Q (pre-scaled) / K (bf16) + transposed split V (fp16)
// qkv=0: plain C write + bias
// ---------------------------------------------------------------------------
#define BK      64
#define NSTG    3
#define KC      (K2 / BK)          // 32
#define TILEB   (128 * BK * 2)     // 16384
#define STAGEB  (2 * TILEB)        // 32768
#define GEMM_SMEM (NSTG * STAGEB)  // 98304

#define CSF     0.18033688011112042f   // 0.125 * log2(e), folded into Q

__global__ __launch_bounds__(256, 2)
void gemm_mma(const float* __restrict__ bias, float* __restrict__ C, int qkv)
{
    extern __shared__ __align__(1024) char smem[];
    const uint32_t sb = smem_u32(smem);

    const int tid  = threadIdx.x;
    const int lane = tid & 31;
    const int wid  = tid >> 5;
    const int wm   = wid & 1;
    const int wn   = wid >> 1;
    const int bm   = blockIdx.y * 128;
    const int bn   = blockIdx.x * 128;

    const __half* Aop = qkv ? g_a2x : g_a2o;
    const __half* Bop = qkv ? g_b2q : g_b2o;

    const int a_row_l = (lane & 7) | (((lane >> 3) & 1) << 3);
    const int a_kb    = (lane >> 4) << 4;
    const int b_row_l = (lane & 7) | (((lane >> 4) & 1) << 3);
    const int b_kb    = ((lane >> 3) & 1) << 4;
    const uint32_t axor = (uint32_t)(a_row_l & 7) << 4;
    const uint32_t bxor = (uint32_t)(b_row_l & 7) << 4;

    float acc[4][4][4];
#pragma unroll
    for (int m = 0; m < 4; m++)
#pragma unroll
        for (int n = 0; n < 4; n++)
#pragma unroll
            for (int r = 0; r < 4; r++) acc[m][n][r] = 0.f;

    auto load_stage = [&](int s, int kc) {
        const uint32_t stg = sb + (uint32_t)s * STAGEB;
#pragma unroll
        for (int i = 0; i < 4; i++) {
            const int idx = tid + i * 256;
            const int row = idx >> 3;
            const int c16 = idx & 7;
            const uint32_t sw = (uint32_t)row * 128 + (((uint32_t)c16 << 4) ^ ((uint32_t)(row & 7) << 4));
            CP_ASYNC16(stg + sw,
                       (const char*)(Aop + (size_t)(bm + row) * K2 + kc) + c16 * 16);
            CP_ASYNC16(stg + TILEB + sw,
                       (const char*)(Bop + (size_t)(bn + row) * K2 + kc) + c16 * 16);
        }
    };

    load_stage(0, 0);      CP_COMMIT();
    load_stage(1, BK);     CP_COMMIT();

    for (int c = 0; c < KC; c++) {
        CP_WAIT(NSTG - 2);
        __syncthreads();

        const int s = c % NSTG;
        const uint32_t sA = sb + (uint32_t)s * STAGEB;
        const uint32_t sB = sA + TILEB;

#pragma unroll
        for (int kk = 0; kk < 4; kk++) {
            uint32_t a[4][4], b[2][4];
#pragma unroll
            for (int mf = 0; mf < 4; mf++)
                LDSM_X4(a[mf][0], a[mf][1], a[mf][2], a[mf][3],
                        sA + (uint32_t)(wm * 64 + mf * 16 + a_row_l) * 128
                           + (((uint32_t)(kk * 32 + a_kb)) ^ axor));
#pragma unroll
            for (int nf2 = 0; nf2 < 2; nf2++)
                LDSM_X4(b[nf2][0], b[nf2][1], b[nf2][2], b[nf2][3],
                        sB + (uint32_t)(wn * 32 + nf2 * 16 + b_row_l) * 128
                           + (((uint32_t)(kk * 32 + b_kb)) ^ bxor));
#pragma unroll
            for (int mf = 0; mf < 4; mf++)
#pragma unroll
                for (int nf = 0; nf < 4; nf++)
                    MMA_F16(acc[mf][nf], a[mf],
                            b[nf >> 1][(nf & 1) * 2], b[nf >> 1][(nf & 1) * 2 + 1]);
        }

        const int nc = c + NSTG - 1;
        if (nc < KC) load_stage(nc % NSTG, nc * BK);
        CP_COMMIT();
    }

    // ------------------ epilogue ------------------
    const int g  = lane >> 2;
    const int cp = (lane & 3) * 2;

#pragma unroll
    for (int mf = 0; mf < 4; mf++) {
#pragma unroll
        for (int half = 0; half < 2; half++) {
            const int row = bm + wm * 64 + mf * 16 + g + half * 8;
#pragma unroll
            for (int nf = 0; nf < 4; nf++) {
                const int col = bn + wn * 32 + nf * 8 + cp;
                float2 o;
                o.x = acc[mf][nf][half * 2 + 0] + bias[col];
                o.y = acc[mf][nf][half * 2 + 1] + bias[col + 1];
                if (qkv) {
                    const int bb = row >> 11;
                    const int n  = row & 2047;
                    const int pt = col >> 10;
                    const int c1 = col & 1023;
                    const int hh = c1 >> 6;
                    const int hd = c1 & 63;          // even
                    const int bh = bb * NHEADS + hh;
                    if (pt < 2) {
                        if (pt == 0) { o.x *= CSF; o.y *= CSF; }   // fold softmax scale into Q
                        __nv_bfloat162 hv = __floats2bfloat162_rn(o.x, o.y);
                        __nv_bfloat162 lv = __floats2bfloat162_rn(
                            o.x - __bfloat162float(hv.x), o.y - __bfloat162float(hv.y));
                        __nv_bfloat16* dst = pt ? g_k2 : g_q2;
                        const size_t base = ((size_t)bh * SEQ + n) * 128;
                        *(__nv_bfloat162*)&dst[base + hd]      = hv;
                        *(__nv_bfloat162*)&dst[base + 64 + hd] = lv;
                    } else {
                        __half2 hv = __floats2half2_rn(o.x, o.y);
                        __half2 lv = __floats2half2_rn(
                            o.x - __half2float(__low2half(hv)),
                            o.y - __half2float(__high2half(hv)));
                        const size_t vb = ((size_t)bh * 64 + hd) * SEQ + n;
                        g_vth[vb]       = __low2half(hv);
                        g_vth[vb + SEQ] = __high2half(hv);
                        g_vtl[vb]       = __low2half(lv);
                        g_vtl[vb + SEQ] = __high2half(lv);
                    }
                } else {
                    *(float2*)&C[(size_t)row * HIDDEN + col] = o;
                }
            }
        }
    }
}

// ---------------------------------------------------------------------------
// Flash attention: QK^T bf16 3-term (merged pass, Q cached in registers),
// PV fp16 2-term. 2-stage K/V pipeline, 2 CTAs/SM. Epilogue writes g_a2o
// in fp16 2-term layout [hi @ col | lo @ col+1024], row stride K2.
// ---------------------------------------------------------------------------
#define NT        (SEQ / 64)       // 32 key tiles
#define ASTG_OFF  32768
#define ASTG_SZ   32768
#define ATTN2_SMEM (32768 + 2 * ASTG_SZ)   // 98304

__global__ __launch_bounds__(256, 2)
void attn_mma()
{
    extern __shared__ __align__(1024) char smem[];
    const uint32_t sb = smem_u32(smem);
    const int tid = threadIdx.x, lane = tid & 31, wid = tid >> 5;
    const int qt = blockIdx.x, h = blockIdx.y, b = blockIdx.z;
    const int bh = b * NHEADS + h;

    const __nv_bfloat16* q2p = g_q2 + ((size_t)bh * SEQ + qt * 128) * 128;
    const __nv_bfloat16* k2p = g_k2 + (size_t)bh * SEQ * 128;
    const __half* vhp = g_vth + (size_t)bh * 64 * SEQ;
    const __half* vlp = g_vtl + (size_t)bh * 64 * SEQ;

    auto load_stage = [&](int kt) {
        const uint32_t stg = sb + ASTG_OFF + (uint32_t)(kt & 1) * ASTG_SZ;
#pragma unroll
        for (int i = 0; i < 8; i++) {
            const int idx = tid + i * 256;                 // 0..2047
            if (idx < 1024) {                              // k2: 64 rows x 16 chunks
                const int row = idx >> 4, c16 = idx & 15;
                CP_ASYNC16(stg + row * 256 + (((uint32_t)c16 << 4) ^ ((uint32_t)(row & 7) << 4)),
                           (const char*)(k2p + (size_t)(kt * 64 + row) * 128) + c16 * 16);
            } else {                                       // vt: 64 d-rows x [Vh 8 | Vl 8] (fp16)
                const int j = idx - 1024;
                const int row = j >> 4, c16 = j & 15;
                const __half* src = (c16 < 8) ? vhp : vlp;
                CP_ASYNC16(stg + 16384 + row * 256 + (((uint32_t)c16 << 4) ^ ((uint32_t)(row & 7) << 4)),
                           (const char*)(src + (size_t)row * SEQ + kt * 64) + (c16 & 7) * 16);
            }
        }
    };

    // Q tile (128 rows x 16 chunks) + first K/V stage in one commit group
#pragma unroll
    for (int i = 0; i < 8; i++) {
        const int idx = tid + i * 256;
        const int row = idx >> 4, c16 = idx & 15;
        CP_ASYNC16(sb + row * 256 + (((uint32_t)c16 << 4) ^ ((uint32_t)(row & 7) << 4)),
                   (const char*)(q2p + (size_t)row * 128) + c16 * 16);
    }
    load_stage(0); CP_COMMIT();

    const int a_row = wid * 16 + ((lane & 7) | (((lane >> 3) & 1) << 3));
    const int a_kb  = lane >> 4;
    const int b_rl  = (lane & 7) | (((lane >> 4) & 1) << 3);
    const int b_kb  = (lane >> 3) & 1;
    const uint32_t a_sw = (uint32_t)(a_row & 7) << 4;
    const uint32_t qbase = sb + (uint32_t)a_row * 256;

    // ---- prologue: wait for Q + stage 0, cache Q fragments in registers ----
    CP_WAIT(0);
    __syncthreads();
    uint32_t qh[4][4], ql[4][4];
#pragma unroll
    for (int kk = 0; kk < 4; kk++) {
        LDSM_X4(qh[kk][0], qh[kk][1], qh[kk][2], qh[kk][3],
                qbase + (((uint32_t)(kk * 2 + a_kb) << 4) ^ a_sw));
        LDSM_X4(ql[kk][0], ql[kk][1], ql[kk][2], ql[kk][3],
                qbase + (((uint32_t)(8 + kk * 2 + a_kb) << 4) ^ a_sw));
    }

    float oacc[8][4];
#pragma unroll
    for (int nf = 0; nf < 8; nf++)
#pragma unroll
        for (int e = 0; e < 4; e++) oacc[nf][e] = 0.f;
    float m0 = -1e30f, m1 = -1e30f, l0 = 0.f, l1 = 0.f;

    for (int kt = 0; kt < NT; kt++) {
        if (kt > 0) {
            CP_WAIT(0);        // stage kt resident
            __syncthreads();   // all warps done with stage kt-1
        }
        if (kt + 1 < NT) { load_stage(kt + 1); CP_COMMIT(); }

        const uint32_t sk = sb + ASTG_OFF + (uint32_t)(kt & 1) * ASTG_SZ;
        const uint32_t sv = sk + 16384;

        // ---- S = Qh·Kh + Ql·Kh + Qh·Kl (bf16, merged single pass) ----
        float s[8][4];
#pragma unroll
        for (int nf = 0; nf < 8; nf++)
#pragma unroll
            for (int e = 0; e < 4; e++) s[nf][e] = 0.f;

#pragma unroll
        for (int kk = 0; kk < 4; kk++) {
#pragma unroll
            for (int nb = 0; nb < 4; nb++) {
                const int br = nb * 16 + b_rl;
                const uint32_t brow = sk + (uint32_t)br * 256;
                const uint32_t bsw  = (uint32_t)(br & 7) << 4;
                uint32_t bk[4];
                LDSM_X4(bk[0], bk[1], bk[2], bk[3],
                        brow + (((uint32_t)(kk * 2 + b_kb) << 4) ^ bsw));
                MMA_BF16(s[2 * nb],     qh[kk], bk[0], bk[1]);
                MMA_BF16(s[2 * nb + 1], qh[kk], bk[2], bk[3]);
                MMA_BF16(s[2 * nb],     ql[kk], bk[0], bk[1]);
                MMA_BF16(s[2 * nb + 1], ql[kk], bk[2], bk[3]);
                LDSM_X4(bk[0], bk[1], bk[2], bk[3],
                        brow + (((uint32_t)(8 + kk * 2 + b_kb) << 4) ^ bsw));
                MMA_BF16(s[2 * nb],     qh[kk], bk[0], bk[1]);
                MMA_BF16(s[2 * nb + 1], qh[kk], bk[2], bk[3]);
            }
        }

        // ---- online softmax (fp32; scale pre-folded into Q) ----
        float rm0 = s[0][0], rm1 = s[0][2];
#pragma unroll
        for (int nf = 0; nf < 8; nf++) {
            rm0 = fmaxf(rm0, fmaxf(s[nf][0], s[nf][1]));
            rm1 = fmaxf(rm1, fmaxf(s[nf][2], s[nf][3]));
        }
        rm0 = fmaxf(rm0, __shfl_xor_sync(0xffffffffu, rm0, 1));
        rm0 = fmaxf(rm0, __shfl_xor_sync(0xffffffffu, rm0, 2));
        rm1 = fmaxf(rm1, __shfl_xor_sync(0xffffffffu, rm1, 1));
        rm1 = fmaxf(rm1, __shfl_xor_sync(0xffffffffu, rm1, 2));
        const float mn0 = fmaxf(m0, rm0);
        const float mn1 = fmaxf(m1, rm1);
        const float cr0 = ex2f(m0 - mn0);
        const float cr1 = ex2f(m1 - mn1);
        float sum0 = 0.f, sum1 = 0.f;
#pragma unroll
        for (int nf = 0; nf < 8; nf++) {
            s[nf][0] = ex2f(s[nf][0] - mn0);
            s[nf][1] = ex2f(s[nf][1] - mn0);
            s[nf][2] = ex2f(s[nf][2] - mn1);
            s[nf][3] = ex2f(s[nf][3] - mn1);
            sum0 += s[nf][0] + s[nf][1];
            sum1 += s[nf][2] + s[nf][3];
        }
        sum0 += __shfl_xor_sync(0xffffffffu, sum0, 1);
        sum0 += __shfl_xor_sync(0xffffffffu, sum0, 2);
        sum1 += __shfl_xor_sync(0xffffffffu, sum1, 1);
        sum1 += __shfl_xor_sync(0xffffffffu, sum1, 2);
        l0 = l0 * cr0 + sum0;  l1 = l1 * cr1 + sum1;
        m0 = mn0;  m1 = mn1;
#pragma unroll
        for (int nf = 0; nf < 8; nf++) {
            oacc[nf][0] *= cr0; oacc[nf][1] *= cr0;
            oacc[nf][2] *= cr1; oacc[nf][3] *= cr1;
        }

        // ---- P -> fp16 A-fragments (single precision, registers) ----
        uint32_t ph[4][4];
#pragma unroll
        for (int t = 0; t < 4; t++) {
#pragma unroll
            for (int hf = 0; hf < 2; hf++) {
                const int j = 2 * t + hf;
                __half2 p0 = __floats2half2_rn(s[j][0], s[j][1]);
                __half2 p1 = __floats2half2_rn(s[j][2], s[j][3]);
                ph[t][hf * 2 + 0] = *reinterpret_cast<uint32_t*>(&p0);
                ph[t][hf * 2 + 1] = *reinterpret_cast<uint32_t*>(&p1);
            }
        }

        // ---- O += P·Vh (fp16), then O += P·Vl — split passes to cap regs ----
#pragma unroll
        for (int t = 0; t < 4; t++) {
            uint32_t bv[4][4];
#pragma unroll
            for (int nb = 0; nb < 4; nb++) {
                const int br = nb * 16 + b_rl;
                LDSM_X4(bv[nb][0], bv[nb][1], bv[nb][2], bv[nb][3],
                        sv + (uint32_t)br * 256 + (((uint32_t)(t * 2 + b_kb) << 4) ^ ((uint32_t)(br & 7) << 4)));
            }
#pragma unroll
            for (int nf = 0; nf < 8; nf++)
                MMA_F16(oacc[nf], ph[t], bv[nf >> 1][(nf & 1) * 2], bv[nf >> 1][(nf & 1) * 2 + 1]);
        }
#pragma unroll
        for (int t = 0; t < 4; t++) {
            uint32_t bv[4][4];
#pragma unroll
            for (int nb = 0; nb < 4; nb++) {
                const int br = nb * 16 + b_rl;
                LDSM_X4(bv[nb][0], bv[nb][1], bv[nb][2], bv[nb][3],
                        sv + (uint32_t)br * 256 + (((uint32_t)(8 + t * 2 + b_kb) << 4) ^ ((uint32_t)(br & 7) << 4)));
            }
#pragma unroll
            for (int nf = 0; nf < 8; nf++)
                MMA_F16(oacc[nf], ph[t], bv[nf >> 1][(nf & 1) * 2], bv[nf >> 1][(nf & 1) * 2 + 1]);
        }
    }

    // ---- epilogue: normalize, write fp16 2-term A operand for O-proj ----
    // layout: hi @ col, lo @ col+1024 (row stride K2)
    const int g = lane >> 2, cp2 = (lane & 3) * 2;
    const float i0 = 1.f / l0, i1 = 1.f / l1;
    const size_t r0 = (size_t)b * SEQ + qt * 128 + wid * 16 + g;
#pragma unroll
    for (int nf = 0; nf < 8; nf++) {
        const int col = h * 64 + nf * 8 + cp2;
        float2 u, v;
        u.x = oacc[nf][0] * i0;  u.y = oacc[nf][1] * i0;
        v.x = oacc[nf][2] * i1;  v.y = oacc[nf][3] * i1;

        __half2 uh = __floats2half2_rn(u.x, u.y);
        __half2 ul = __floats2half2_rn(u.x - __half2float(__low2half(uh)),
                                       u.y - __half2float(__high2half(uh)));
        __half2 vh = __floats2half2_rn(v.x, v.y);
        __half2 vl = __floats2half2_rn(v.x - __half2float(__low2half(vh)),
                                       v.y - __half2float(__high2half(vh)));

        __half* d0 = g_a2o + r0 * K2;
        __half* d1 = g_a2o + (r0 + 8) * K2;
        *(__half2*)&d0[col]        = uh;
        *(__half2*)&d0[col + 1024] = ul;
        *(__half2*)&d1[col]        = vh;
        *(__half2*)&d1[col + 1024] = vl;
    }
}

// ---------------------------------------------------------------------------
// Launch
// ---------------------------------------------------------------------------
extern "C" void kernel_launch(void* const* d_in, const int* in_sizes, int n_in,
                              void* d_out, int out_size)
{
    const float* x    = (const float*)d_in[0];
    const float* Wqkv = (const float*)d_in[1];
    const float* bqkv = (const float*)d_in[2];
    const float* Wo   = (const float*)d_in[3];
    const float* bo   = (const float*)d_in[4];
    float* out = (float*)d_out;

    cudaFuncSetAttribute(gemm_mma, cudaFuncAttributeMaxDynamicSharedMemorySize, GEMM_SMEM);
    cudaFuncSetAttribute(attn_mma, cudaFuncAttributeMaxDynamicSharedMemorySize, ATTN2_SMEM);

    // fp16 2-term operand prep
    split2_kernel<<<MROWS, 256>>>((const float4*)x,    0, MROWS * 256);
    split2_kernel<<<3 * HIDDEN, 256>>>((const float4*)Wqkv, 1, 3 * HIDDEN * 256);
    split2_kernel<<<HIDDEN, 256>>>((const float4*)Wo,  2, HIDDEN * 256);

    // QKV projection -> split attention operands (q2 scaled, k2 bf16, vth/vtl fp16)
    gemm_mma<<<dim3(3 * HIDDEN / 128, MROWS / 128), 256, GEMM_SMEM>>>(bqkv, nullptr, 1);

    // attention on tensor cores -> fp16 2-term O-proj A operand (g_a2o)
    attn_mma<<<dim3(SEQ / 128, NHEADS, BATCH), 256, ATTN2_SMEM>>>();

    // O-projection
    gemm_mma<<<dim3(HIDDEN / 128, MROWS / 128), 256, GEMM_SMEM>>>(bo, out, 0);
}